// round 4
// baseline (speedup 1.0000x reference)
#include <cuda_runtime.h>
#include <stdint.h>

// Problem constants (fixed by the reference)
#define N_NODES   100000
#define IN_CH     2048
#define OUT_CH    128
#define NNZ_FEAT  2000000
#define NNZ_ADJ   1600000

// Ping-pong scratch for h (51.2 MB each). __device__ globals = no runtime alloc.
__device__ float g_h0[(size_t)N_NODES * OUT_CH];
__device__ float g_h1[(size_t)N_NODES * OUT_CH];

// Vectorized global reduction (sm_90+): one 16B red op instead of 4 scalar atomics.
__device__ __forceinline__ void red_add_v4(float* addr, float4 v) {
    asm volatile("red.global.add.v4.f32 [%0], {%1,%2,%3,%4};"
                 :: "l"(addr), "f"(v.x), "f"(v.y), "f"(v.z), "f"(v.w)
                 : "memory");
}

// COO SpMM: out[row,:] += val * dense[col,:]   (dense rows are OUT_CH=128 floats)
// One warp per nonzero. Lane l handles floats [4l, 4l+4).
__global__ void __launch_bounds__(256, 8)
spmm_coo_kernel(const int* __restrict__ rows,
                const int* __restrict__ cols,
                const float* __restrict__ vals,
                const float* __restrict__ dense,
                float* __restrict__ out,
                int nnz)
{
    int gtid = blockIdx.x * blockDim.x + threadIdx.x;
    int w    = gtid >> 5;
    int lane = gtid & 31;
    if (w >= nnz) return;

    // All lanes load the same triple: single-sector broadcast within the warp,
    // and adjacent warps in the block share cache lines.
    int   r = __ldg(rows + w);
    int   c = __ldg(cols + w);
    float v = __ldg(vals + w);

    const float4* drow = reinterpret_cast<const float4*>(dense + (size_t)c * OUT_CH);
    float4 d = __ldg(drow + lane);

    float4 contrib = make_float4(v * d.x, v * d.y, v * d.z, v * d.w);
    red_add_v4(out + (size_t)r * OUT_CH + (lane << 2), contrib);
}

// h = relu(h + bias)   elementwise over N_NODES*OUT_CH; bias broadcast over rows.
__global__ void __launch_bounds__(256)
bias_relu_kernel(float* __restrict__ h, const float* __restrict__ bias, int total)
{
    int i = blockIdx.x * blockDim.x + threadIdx.x;
    // Process as float4: total is divisible by 4 (OUT_CH=128).
    int i4 = i << 2;
    if (i4 >= total) return;
    float4 hv = *reinterpret_cast<float4*>(h + i4);
    int b0 = i4 & (OUT_CH - 1);
    float4 bv = *reinterpret_cast<const float4*>(bias + b0);
    hv.x = fmaxf(hv.x + bv.x, 0.0f);
    hv.y = fmaxf(hv.y + bv.y, 0.0f);
    hv.z = fmaxf(hv.z + bv.z, 0.0f);
    hv.w = fmaxf(hv.w + bv.w, 0.0f);
    *reinterpret_cast<float4*>(h + i4) = hv;
}

extern "C" void kernel_launch(void* const* d_in, const int* in_sizes, int n_in,
                              void* d_out, int out_size)
{
    const int*   feat_rows = (const int*)  d_in[0];
    const int*   feat_cols = (const int*)  d_in[1];
    const float* feat_vals = (const float*)d_in[2];
    const int*   adj_rows  = (const int*)  d_in[3];
    const int*   adj_cols  = (const int*)  d_in[4];
    const float* adj_vals  = (const float*)d_in[5];
    const float* weight    = (const float*)d_in[6];
    const float* bias      = (const float*)d_in[7];
    float*       out       = (float*)      d_out;

    float *h0, *h1;
    cudaGetSymbolAddress((void**)&h0, g_h0);
    cudaGetSymbolAddress((void**)&h1, g_h1);

    const size_t h_bytes = (size_t)N_NODES * OUT_CH * sizeof(float);
    const int    h_elems = N_NODES * OUT_CH;

    // grid sizing: one warp per nnz, 256-thread blocks (8 warps)
    const int feat_blocks = (NNZ_FEAT * 32 + 255) / 256;   // 250000
    const int adj_blocks  = (NNZ_ADJ  * 32 + 255) / 256;   // 200000
    const int ew_blocks   = (h_elems / 4 + 255) / 256;

    // Layer 1: h0 = relu(spmm(feat, W) + bias)
    cudaMemsetAsync(h0, 0, h_bytes);
    spmm_coo_kernel<<<feat_blocks, 256>>>(feat_rows, feat_cols, feat_vals,
                                          weight, h0, NNZ_FEAT);
    bias_relu_kernel<<<ew_blocks, 256>>>(h0, bias, h_elems);

    // Iteration 2: h1 = adj @ h0
    cudaMemsetAsync(h1, 0, h_bytes);
    spmm_coo_kernel<<<adj_blocks, 256>>>(adj_rows, adj_cols, adj_vals,
                                         h0, h1, NNZ_ADJ);

    // Iteration 3: h0 = adj @ h1
    cudaMemsetAsync(h0, 0, h_bytes);
    spmm_coo_kernel<<<adj_blocks, 256>>>(adj_rows, adj_cols, adj_vals,
                                         h1, h0, NNZ_ADJ);

    // Iteration 4: out = adj @ h0   (d_out is poisoned -> zero first)
    cudaMemsetAsync(out, 0, (size_t)out_size * sizeof(float));
    spmm_coo_kernel<<<adj_blocks, 256>>>(adj_rows, adj_cols, adj_vals,
                                         h0, out, NNZ_ADJ);
}

// round 5
// speedup vs baseline: 2.3508x; 2.3508x over previous
#include <cuda_runtime.h>
#include <stdint.h>

// Problem constants (fixed by the reference)
#define N_NODES   100000
#define IN_CH     2048
#define OUT_CH    128
#define NNZ_FEAT  2000000
#define NNZ_ADJ   1600000

#define SCAN_BLOCK 1024
#define SCAN_NBLK  ((N_NODES + SCAN_BLOCK - 1) / SCAN_BLOCK)   // 98

// ---------------- device scratch (no runtime allocation allowed) ------------
__device__ float g_h0[(size_t)N_NODES * OUT_CH];   // 51.2 MB
__device__ float g_h1[(size_t)N_NODES * OUT_CH];   // 51.2 MB

__device__ int2 g_feat_pack[NNZ_FEAT];             // 16 MB  (col, val-bits) row-sorted
__device__ int2 g_adj_pack[NNZ_ADJ];               // 12.8 MB

__device__ int g_rowptr_feat[N_NODES + 1];
__device__ int g_rowptr_adj[N_NODES + 1];
__device__ int g_cursor[N_NODES];                  // scatter cursors (rebuilt per matrix)
__device__ int g_cnt[N_NODES];                     // histogram scratch
__device__ int g_incl[N_NODES];                    // inclusive-scan scratch
__device__ int g_bsum[SCAN_NBLK + 1];              // per-block sums

// ---------------- CSR build: histogram -> scan -> scatter -------------------
__global__ void __launch_bounds__(256)
hist_kernel(const int* __restrict__ rows, int nnz, int* __restrict__ cnt)
{
    int i = blockIdx.x * blockDim.x + threadIdx.x;
    if (i < nnz) atomicAdd(cnt + rows[i], 1);
}

// Phase A: per-block inclusive scan (Hillis-Steele), emit block sums.
__global__ void __launch_bounds__(SCAN_BLOCK)
scan_block_kernel(const int* __restrict__ cnt, int* __restrict__ incl,
                  int* __restrict__ bsum, int n)
{
    __shared__ int s[SCAN_BLOCK];
    int i = blockIdx.x * SCAN_BLOCK + threadIdx.x;
    int x = (i < n) ? cnt[i] : 0;
    s[threadIdx.x] = x;
    __syncthreads();
    #pragma unroll
    for (int off = 1; off < SCAN_BLOCK; off <<= 1) {
        int t = (threadIdx.x >= off) ? s[threadIdx.x - off] : 0;
        __syncthreads();
        s[threadIdx.x] += t;
        __syncthreads();
    }
    if (i < n) incl[i] = s[threadIdx.x];
    if (threadIdx.x == SCAN_BLOCK - 1) bsum[blockIdx.x] = s[SCAN_BLOCK - 1];
}

// Phase B: exclusive scan of the (tiny) block-sum array, single thread.
__global__ void scan_bsum_kernel(int* __restrict__ bsum, int nb)
{
    if (blockIdx.x == 0 && threadIdx.x == 0) {
        int run = 0;
        for (int i = 0; i < nb; i++) { int t = bsum[i]; bsum[i] = run; run += t; }
    }
}

// Phase C: rowptr[i] = exclusive prefix; also seed the scatter cursor.
__global__ void __launch_bounds__(256)
finalize_kernel(const int* __restrict__ cnt, const int* __restrict__ incl,
                const int* __restrict__ bsum, int* __restrict__ rowptr,
                int* __restrict__ cursor, int n, int nnz)
{
    int i = blockIdx.x * blockDim.x + threadIdx.x;
    if (i < n) {
        int ex = incl[i] - cnt[i] + bsum[i / SCAN_BLOCK];
        rowptr[i] = ex;
        cursor[i] = ex;
    }
    if (i == 0) rowptr[n] = nnz;
}

__global__ void __launch_bounds__(256)
scatter_kernel(const int* __restrict__ rows, const int* __restrict__ cols,
               const float* __restrict__ vals, int nnz,
               int* __restrict__ cursor, int2* __restrict__ pack)
{
    int i = blockIdx.x * blockDim.x + threadIdx.x;
    if (i >= nnz) return;
    int r = rows[i];
    int p = atomicAdd(cursor + r, 1);
    pack[p] = make_int2(cols[i], __float_as_int(vals[i]));
}

// ---------------- gather SpMM: one warp per output row ----------------------
// out[r,:] = sum_j val_j * dense[col_j,:]      (dense rows = 128 floats)
// Lane l owns floats [4l, 4l+4). Inner loop: 32 packed entries staged per-lane,
// then 4-way unrolled shfl-broadcast + 4 independent LDG.128 gathers (MLP=4).
template<bool RELU_BIAS>
__global__ void __launch_bounds__(256)
spmm_gather_kernel(const int* __restrict__ rowptr, const int2* __restrict__ pack,
                   const float* __restrict__ dense, const float* __restrict__ bias,
                   float* __restrict__ out, int n_rows)
{
    int w    = (blockIdx.x * blockDim.x + threadIdx.x) >> 5;
    int lane = threadIdx.x & 31;
    if (w >= n_rows) return;

    int start = __ldg(rowptr + w);
    int end   = __ldg(rowptr + w + 1);

    float4 acc = make_float4(0.f, 0.f, 0.f, 0.f);

    for (int base = start; base < end; base += 32) {
        int n = end - base; if (n > 32) n = 32;
        int2 p = make_int2(0, 0);
        if (lane < n) p = __ldg(pack + base + lane);

        int k = 0;
        for (; k + 4 <= n; k += 4) {
            int   c0 = __shfl_sync(0xffffffffu, p.x, k);
            int   c1 = __shfl_sync(0xffffffffu, p.x, k + 1);
            int   c2 = __shfl_sync(0xffffffffu, p.x, k + 2);
            int   c3 = __shfl_sync(0xffffffffu, p.x, k + 3);
            float v0 = __int_as_float(__shfl_sync(0xffffffffu, p.y, k));
            float v1 = __int_as_float(__shfl_sync(0xffffffffu, p.y, k + 1));
            float v2 = __int_as_float(__shfl_sync(0xffffffffu, p.y, k + 2));
            float v3 = __int_as_float(__shfl_sync(0xffffffffu, p.y, k + 3));
            float4 d0 = __ldg(reinterpret_cast<const float4*>(dense + (size_t)c0 * OUT_CH) + lane);
            float4 d1 = __ldg(reinterpret_cast<const float4*>(dense + (size_t)c1 * OUT_CH) + lane);
            float4 d2 = __ldg(reinterpret_cast<const float4*>(dense + (size_t)c2 * OUT_CH) + lane);
            float4 d3 = __ldg(reinterpret_cast<const float4*>(dense + (size_t)c3 * OUT_CH) + lane);
            acc.x += v0 * d0.x; acc.y += v0 * d0.y; acc.z += v0 * d0.z; acc.w += v0 * d0.w;
            acc.x += v1 * d1.x; acc.y += v1 * d1.y; acc.z += v1 * d1.z; acc.w += v1 * d1.w;
            acc.x += v2 * d2.x; acc.y += v2 * d2.y; acc.z += v2 * d2.z; acc.w += v2 * d2.w;
            acc.x += v3 * d3.x; acc.y += v3 * d3.y; acc.z += v3 * d3.z; acc.w += v3 * d3.w;
        }
        for (; k < n; k++) {
            int   c0 = __shfl_sync(0xffffffffu, p.x, k);
            float v0 = __int_as_float(__shfl_sync(0xffffffffu, p.y, k));
            float4 d0 = __ldg(reinterpret_cast<const float4*>(dense + (size_t)c0 * OUT_CH) + lane);
            acc.x += v0 * d0.x; acc.y += v0 * d0.y; acc.z += v0 * d0.z; acc.w += v0 * d0.w;
        }
    }

    if (RELU_BIAS) {
        float4 b = __ldg(reinterpret_cast<const float4*>(bias) + lane);
        acc.x = fmaxf(acc.x + b.x, 0.f);
        acc.y = fmaxf(acc.y + b.y, 0.f);
        acc.z = fmaxf(acc.z + b.z, 0.f);
        acc.w = fmaxf(acc.w + b.w, 0.f);
    }
    reinterpret_cast<float4*>(out + (size_t)w * OUT_CH)[lane] = acc;
}

// ---------------- launch ----------------------------------------------------
static void build_csr(const int* rows, const int* cols, const float* vals,
                      int nnz, int* rowptr, int2* pack,
                      int* cnt, int* incl, int* bsum, int* cursor)
{
    cudaMemsetAsync(cnt, 0, N_NODES * sizeof(int));
    hist_kernel<<<(nnz + 255) / 256, 256>>>(rows, nnz, cnt);
    scan_block_kernel<<<SCAN_NBLK, SCAN_BLOCK>>>(cnt, incl, bsum, N_NODES);
    scan_bsum_kernel<<<1, 32>>>(bsum, SCAN_NBLK);
    finalize_kernel<<<(N_NODES + 255) / 256, 256>>>(cnt, incl, bsum, rowptr, cursor,
                                                    N_NODES, nnz);
    scatter_kernel<<<(nnz + 255) / 256, 256>>>(rows, cols, vals, nnz, cursor, pack);
}

extern "C" void kernel_launch(void* const* d_in, const int* in_sizes, int n_in,
                              void* d_out, int out_size)
{
    const int*   feat_rows = (const int*)  d_in[0];
    const int*   feat_cols = (const int*)  d_in[1];
    const float* feat_vals = (const float*)d_in[2];
    const int*   adj_rows  = (const int*)  d_in[3];
    const int*   adj_cols  = (const int*)  d_in[4];
    const float* adj_vals  = (const float*)d_in[5];
    const float* weight    = (const float*)d_in[6];
    const float* bias      = (const float*)d_in[7];
    float*       out       = (float*)      d_out;

    float *h0, *h1;
    int *rp_f, *rp_a, *cnt, *incl, *bsum, *cursor;
    int2 *pk_f, *pk_a;
    cudaGetSymbolAddress((void**)&h0,     g_h0);
    cudaGetSymbolAddress((void**)&h1,     g_h1);
    cudaGetSymbolAddress((void**)&rp_f,   g_rowptr_feat);
    cudaGetSymbolAddress((void**)&rp_a,   g_rowptr_adj);
    cudaGetSymbolAddress((void**)&cnt,    g_cnt);
    cudaGetSymbolAddress((void**)&incl,   g_incl);
    cudaGetSymbolAddress((void**)&bsum,   g_bsum);
    cudaGetSymbolAddress((void**)&cursor, g_cursor);
    cudaGetSymbolAddress((void**)&pk_f,   g_feat_pack);
    cudaGetSymbolAddress((void**)&pk_a,   g_adj_pack);

    // Build row-sorted CSR for both sparse matrices (in-graph, ~50 us total).
    build_csr(feat_rows, feat_cols, feat_vals, NNZ_FEAT, rp_f, pk_f,
              cnt, incl, bsum, cursor);
    build_csr(adj_rows, adj_cols, adj_vals, NNZ_ADJ, rp_a, pk_a,
              cnt, incl, bsum, cursor);

    const int gather_blocks = (N_NODES * 32 + 255) / 256;   // one warp per row

    // Layer 1: h0 = relu(feat @ W + bias)   (bias+relu fused in epilogue)
    spmm_gather_kernel<true><<<gather_blocks, 256>>>(rp_f, pk_f, weight, bias,
                                                     h0, N_NODES);
    // Iterations 2..4: h = adj @ h   (no atomics, no memsets — every row written)
    spmm_gather_kernel<false><<<gather_blocks, 256>>>(rp_a, pk_a, h0, nullptr,
                                                      h1, N_NODES);
    spmm_gather_kernel<false><<<gather_blocks, 256>>>(rp_a, pk_a, h1, nullptr,
                                                      h0, N_NODES);
    spmm_gather_kernel<false><<<gather_blocks, 256>>>(rp_a, pk_a, h0, nullptr,
                                                      out, N_NODES);
}

// round 9
// speedup vs baseline: 3.0592x; 1.3013x over previous
#include <cuda_runtime.h>
#include <cuda_fp16.h>
#include <stdint.h>

// Problem constants (fixed by the reference)
#define N_NODES   100000
#define IN_CH     2048
#define OUT_CH    128
#define NNZ_FEAT  2000000
#define NNZ_ADJ   1600000

#define SCAN_BLOCK 1024
#define SCAN_NBLK  ((N_NODES + SCAN_BLOCK - 1) / SCAN_BLOCK)   // 98

// ---------------- device scratch (no runtime allocation allowed) ------------
__device__ __half g_h0[(size_t)N_NODES * OUT_CH];   // 25.6 MB fp16 intermediates
__device__ __half g_h1[(size_t)N_NODES * OUT_CH];   // 25.6 MB
__device__ __half g_Wh[(size_t)IN_CH * OUT_CH];     // 0.5 MB fp16 copy of W

__device__ int2 g_feat_pack[NNZ_FEAT];              // (col, fp32-val-bits) row-sorted
__device__ int2 g_adj_pack[NNZ_ADJ];

__device__ int g_rowptr_feat[N_NODES + 1];
__device__ int g_rowptr_adj[N_NODES + 1];
__device__ int g_cursor[N_NODES];
__device__ int g_cnt[N_NODES];
__device__ int g_incl[N_NODES];
__device__ int g_bsum[SCAN_NBLK + 1];

// ---------------- CSR build: histogram -> scan -> scatter -------------------
__global__ void __launch_bounds__(256)
hist_kernel(const int* __restrict__ rows, int nnz, int* __restrict__ cnt)
{
    int i = blockIdx.x * blockDim.x + threadIdx.x;
    if (i < nnz) atomicAdd(cnt + rows[i], 1);
}

__global__ void __launch_bounds__(SCAN_BLOCK)
scan_block_kernel(const int* __restrict__ cnt, int* __restrict__ incl,
                  int* __restrict__ bsum, int n)
{
    __shared__ int s[SCAN_BLOCK];
    int i = blockIdx.x * SCAN_BLOCK + threadIdx.x;
    int x = (i < n) ? cnt[i] : 0;
    s[threadIdx.x] = x;
    __syncthreads();
    #pragma unroll
    for (int off = 1; off < SCAN_BLOCK; off <<= 1) {
        int t = (threadIdx.x >= off) ? s[threadIdx.x - off] : 0;
        __syncthreads();
        s[threadIdx.x] += t;
        __syncthreads();
    }
    if (i < n) incl[i] = s[threadIdx.x];
    if (threadIdx.x == SCAN_BLOCK - 1) bsum[blockIdx.x] = s[SCAN_BLOCK - 1];
}

__global__ void scan_bsum_kernel(int* __restrict__ bsum, int nb)
{
    if (blockIdx.x == 0 && threadIdx.x == 0) {
        int run = 0;
        for (int i = 0; i < nb; i++) { int t = bsum[i]; bsum[i] = run; run += t; }
    }
}

__global__ void __launch_bounds__(256)
finalize_kernel(const int* __restrict__ cnt, const int* __restrict__ incl,
                const int* __restrict__ bsum, int* __restrict__ rowptr,
                int* __restrict__ cursor, int n, int nnz)
{
    int i = blockIdx.x * blockDim.x + threadIdx.x;
    if (i < n) {
        int ex = incl[i] - cnt[i] + bsum[i / SCAN_BLOCK];
        rowptr[i] = ex;
        cursor[i] = ex;
    }
    if (i == 0) rowptr[n] = nnz;
}

__global__ void __launch_bounds__(256)
scatter_kernel(const int* __restrict__ rows, const int* __restrict__ cols,
               const float* __restrict__ vals, int nnz,
               int* __restrict__ cursor, int2* __restrict__ pack)
{
    int i = blockIdx.x * blockDim.x + threadIdx.x;
    if (i >= nnz) return;
    int r = rows[i];
    int p = atomicAdd(cursor + r, 1);
    pack[p] = make_int2(cols[i], __float_as_int(vals[i]));
}

// ---------------- W fp32 -> fp16 conversion ---------------------------------
__global__ void __launch_bounds__(256)
convert_w_kernel(const float* __restrict__ w, __half* __restrict__ wh, int n)
{
    int i = blockIdx.x * blockDim.x + threadIdx.x;
    if (i < n) wh[i] = __float2half_rn(w[i]);
}

// ---------------- gather SpMM (fp16 dense operand) --------------------------
// out[r,:] = sum_j val_j * dense[col_j,:]   dense rows = 128 halves = 256B.
// One warp per output row; lane l owns channels [4l, 4l+4) (one uint2 = 4 halves).
// Accumulation fp32. OUT_HALF selects fp16 (intermediate) vs fp32 (final) store.
__device__ __forceinline__ void fma_row(float4& acc, float v, uint2 d)
{
    __half2 lo = *reinterpret_cast<__half2*>(&d.x);
    __half2 hi = *reinterpret_cast<__half2*>(&d.y);
    float2 f0 = __half22float2(lo);
    float2 f1 = __half22float2(hi);
    acc.x += v * f0.x; acc.y += v * f0.y;
    acc.z += v * f1.x; acc.w += v * f1.y;
}

template<bool RELU_BIAS, bool OUT_HALF>
__global__ void __launch_bounds__(256)
spmm_gather_kernel(const int* __restrict__ rowptr, const int2* __restrict__ pack,
                   const __half* __restrict__ dense, const float* __restrict__ bias,
                   void* __restrict__ outv, int n_rows)
{
    int w    = (blockIdx.x * blockDim.x + threadIdx.x) >> 5;
    int lane = threadIdx.x & 31;
    if (w >= n_rows) return;

    int start = __ldg(rowptr + w);
    int end   = __ldg(rowptr + w + 1);

    float4 acc = make_float4(0.f, 0.f, 0.f, 0.f);

    for (int base = start; base < end; base += 32) {
        int n = end - base; if (n > 32) n = 32;
        int2 p = make_int2(0, 0);
        if (lane < n) p = __ldg(pack + base + lane);

        int k = 0;
        for (; k + 4 <= n; k += 4) {
            int   c0 = __shfl_sync(0xffffffffu, p.x, k);
            int   c1 = __shfl_sync(0xffffffffu, p.x, k + 1);
            int   c2 = __shfl_sync(0xffffffffu, p.x, k + 2);
            int   c3 = __shfl_sync(0xffffffffu, p.x, k + 3);
            float v0 = __int_as_float(__shfl_sync(0xffffffffu, p.y, k));
            float v1 = __int_as_float(__shfl_sync(0xffffffffu, p.y, k + 1));
            float v2 = __int_as_float(__shfl_sync(0xffffffffu, p.y, k + 2));
            float v3 = __int_as_float(__shfl_sync(0xffffffffu, p.y, k + 3));
            uint2 d0 = __ldg(reinterpret_cast<const uint2*>(dense + (size_t)c0 * OUT_CH) + lane);
            uint2 d1 = __ldg(reinterpret_cast<const uint2*>(dense + (size_t)c1 * OUT_CH) + lane);
            uint2 d2 = __ldg(reinterpret_cast<const uint2*>(dense + (size_t)c2 * OUT_CH) + lane);
            uint2 d3 = __ldg(reinterpret_cast<const uint2*>(dense + (size_t)c3 * OUT_CH) + lane);
            fma_row(acc, v0, d0);
            fma_row(acc, v1, d1);
            fma_row(acc, v2, d2);
            fma_row(acc, v3, d3);
        }
        for (; k < n; k++) {
            int   c0 = __shfl_sync(0xffffffffu, p.x, k);
            float v0 = __int_as_float(__shfl_sync(0xffffffffu, p.y, k));
            uint2 d0 = __ldg(reinterpret_cast<const uint2*>(dense + (size_t)c0 * OUT_CH) + lane);
            fma_row(acc, v0, d0);
        }
    }

    if (RELU_BIAS) {
        float4 b = __ldg(reinterpret_cast<const float4*>(bias) + lane);
        acc.x = fmaxf(acc.x + b.x, 0.f);
        acc.y = fmaxf(acc.y + b.y, 0.f);
        acc.z = fmaxf(acc.z + b.z, 0.f);
        acc.w = fmaxf(acc.w + b.w, 0.f);
    }

    if (OUT_HALF) {
        __half2 lo = __floats2half2_rn(acc.x, acc.y);
        __half2 hi = __floats2half2_rn(acc.z, acc.w);
        uint2 st;
        st.x = *reinterpret_cast<uint32_t*>(&lo);
        st.y = *reinterpret_cast<uint32_t*>(&hi);
        reinterpret_cast<uint2*>(outv)[(size_t)w * 32 + lane] = st;
    } else {
        reinterpret_cast<float4*>(outv)[(size_t)w * 32 + lane] = acc;
    }
}

// ---------------- launch ----------------------------------------------------
static void build_csr(const int* rows, const int* cols, const float* vals,
                      int nnz, int* rowptr, int2* pack,
                      int* cnt, int* incl, int* bsum, int* cursor)
{
    cudaMemsetAsync(cnt, 0, N_NODES * sizeof(int));
    hist_kernel<<<(nnz + 255) / 256, 256>>>(rows, nnz, cnt);
    scan_block_kernel<<<SCAN_NBLK, SCAN_BLOCK>>>(cnt, incl, bsum, N_NODES);
    scan_bsum_kernel<<<1, 32>>>(bsum, SCAN_NBLK);
    finalize_kernel<<<(N_NODES + 255) / 256, 256>>>(cnt, incl, bsum, rowptr, cursor,
                                                    N_NODES, nnz);
    scatter_kernel<<<(nnz + 255) / 256, 256>>>(rows, cols, vals, nnz, cursor, pack);
}

extern "C" void kernel_launch(void* const* d_in, const int* in_sizes, int n_in,
                              void* d_out, int out_size)
{
    const int*   feat_rows = (const int*)  d_in[0];
    const int*   feat_cols = (const int*)  d_in[1];
    const float* feat_vals = (const float*)d_in[2];
    const int*   adj_rows  = (const int*)  d_in[3];
    const int*   adj_cols  = (const int*)  d_in[4];
    const float* adj_vals  = (const float*)d_in[5];
    const float* weight    = (const float*)d_in[6];
    const float* bias      = (const float*)d_in[7];
    float*       out       = (float*)      d_out;

    __half *h0, *h1, *wh;
    int *rp_f, *rp_a, *cnt, *incl, *bsum, *cursor;
    int2 *pk_f, *pk_a;
    cudaGetSymbolAddress((void**)&h0,     g_h0);
    cudaGetSymbolAddress((void**)&h1,     g_h1);
    cudaGetSymbolAddress((void**)&wh,     g_Wh);
    cudaGetSymbolAddress((void**)&rp_f,   g_rowptr_feat);
    cudaGetSymbolAddress((void**)&rp_a,   g_rowptr_adj);
    cudaGetSymbolAddress((void**)&cnt,    g_cnt);
    cudaGetSymbolAddress((void**)&incl,   g_incl);
    cudaGetSymbolAddress((void**)&bsum,   g_bsum);
    cudaGetSymbolAddress((void**)&cursor, g_cursor);
    cudaGetSymbolAddress((void**)&pk_f,   g_feat_pack);
    cudaGetSymbolAddress((void**)&pk_a,   g_adj_pack);

    // W -> fp16 (0.26M elements, ~3 us)
    convert_w_kernel<<<(IN_CH * OUT_CH + 255) / 256, 256>>>(weight, wh, IN_CH * OUT_CH);

    // Row-sorted CSR for both sparse matrices.
    build_csr(feat_rows, feat_cols, feat_vals, NNZ_FEAT, rp_f, pk_f,
              cnt, incl, bsum, cursor);
    build_csr(adj_rows, adj_cols, adj_vals, NNZ_ADJ, rp_a, pk_a,
              cnt, incl, bsum, cursor);

    const int gather_blocks = (N_NODES * 32 + 255) / 256;   // one warp per row

    // Layer 1: h0 = relu(feat @ W + bias), stored fp16
    spmm_gather_kernel<true,  true ><<<gather_blocks, 256>>>(rp_f, pk_f, wh, bias,
                                                             h0, N_NODES);
    // Iterations 2..3: fp16 -> fp16
    spmm_gather_kernel<false, true ><<<gather_blocks, 256>>>(rp_a, pk_a, h0, nullptr,
                                                             h1, N_NODES);
    spmm_gather_kernel<false, true ><<<gather_blocks, 256>>>(rp_a, pk_a, h1, nullptr,
                                                             h0, N_NODES);
    // Iteration 4: fp16 -> fp32 final output (no quantization on last write)
    spmm_gather_kernel<false, false><<<gather_blocks, 256>>>(rp_a, pk_a, h0, nullptr,
                                                             out, N_NODES);
}